// round 7
// baseline (speedup 1.0000x reference)
#include <cuda_runtime.h>
#include <cstdint>

// Problem constants
#define T_STEPS 512
#define BATCH   256
#define INPUT_  256
#define HID_    64
#define GATES_  256            // 4*HID
#define OUT_    1024
#define M_ROWS  (T_STEPS * BATCH)          // 131072
#define OUT_ELEMS ((size_t)M_ROWS * OUT_)  // 134217728
#define HC_ELEMS  (BATCH * HID_)           // 16384

// Scratch (allocation-free rule: __device__ globals)
__device__ float g_xg[(size_t)M_ROWS * GATES_];  // 134 MB: x @ W_ih^T + (b_ih+b_hh)
__device__ float g_hs[(size_t)M_ROWS * HID_];    // 33.5 MB: per-step hidden states

// ---------- f32x2 packed-FMA helpers (full-rate fp32 on sm_103a) ----------
__device__ __forceinline__ unsigned long long pk(float x, float y) {
    unsigned long long r;
    asm("mov.b64 %0, {%1, %2};" : "=l"(r) : "f"(x), "f"(y));
    return r;
}
__device__ __forceinline__ void fma2(unsigned long long& d,
                                     unsigned long long a,
                                     unsigned long long b) {
    asm("fma.rn.f32x2 %0, %1, %2, %0;" : "+l"(d) : "l"(a), "l"(b));
}
__device__ __forceinline__ float2 upk(unsigned long long v) {
    float2 r;
    asm("mov.b64 {%0, %1}, %2;" : "=f"(r.x), "=f"(r.y) : "l"(v));
    return r;
}
__device__ __forceinline__ float sigm(float x) {
    return 1.0f / (1.0f + __expf(-x));
}

// ---------- Generic fp32 GEMM: C[m][n] = act( A[m][K]·B[n][K] + bias ) ----------
// Block tile 128x128, micro tile 8x8, BK=32 staged through smem.
// K is packed in pairs: accumulator lanes hold even-k / odd-k partial sums.
template <int K, int N, bool SIG>
__device__ __forceinline__ void gemm_body(const float* __restrict__ A,
                                          const float* __restrict__ B,
                                          const float* __restrict__ b1,
                                          const float* __restrict__ b2,
                                          float* __restrict__ C) {
    constexpr int LD = 130;  // float2 units per k2-row (pad vs 128 to break conflicts)
    __shared__ unsigned long long As[16 * LD];  // [k2][m]      (m contiguous)
    __shared__ unsigned long long Bs[16 * LD];  // [k2][p(n)]   p(n)=(n&7)*16 + n>>3

    const int tid = threadIdx.x;
    const int tx = tid & 15;        // n-group: cols n0 + 8*tx + j
    const int ty = tid >> 4;        // m-group: rows m0 + 8*ty + i
    const int m0 = blockIdx.y * 128;
    const int n0 = blockIdx.x * 128;

    unsigned long long acc[8][8];
#pragma unroll
    for (int i = 0; i < 8; i++)
#pragma unroll
        for (int j = 0; j < 8; j++) acc[i][j] = 0ull;

    const int r  = tid >> 3;  // 0..31 row within load pass
    const int c4 = tid & 7;   // 0..7  float4 index along k

    for (int kt = 0; kt < K; kt += 32) {
        // Load 128x32 tiles of A and B, pair-transposed into smem
#pragma unroll
        for (int p = 0; p < 4; p++) {
            int row = r + p * 32;
            float4 va = *(const float4*)(A + (size_t)(m0 + row) * K + kt + c4 * 4);
            As[(2 * c4) * LD + row]     = pk(va.x, va.y);
            As[(2 * c4 + 1) * LD + row] = pk(va.z, va.w);
            float4 vb = *(const float4*)(B + (size_t)(n0 + row) * K + kt + c4 * 4);
            int pn = ((row & 7) << 4) + (row >> 3);
            Bs[(2 * c4) * LD + pn]     = pk(vb.x, vb.y);
            Bs[(2 * c4 + 1) * LD + pn] = pk(vb.z, vb.w);
        }
        __syncthreads();

#pragma unroll
        for (int k2 = 0; k2 < 16; k2++) {
            unsigned long long au[8], bu[8];
            const ulonglong2* ap = (const ulonglong2*)(As + k2 * LD + ty * 8);
#pragma unroll
            for (int q = 0; q < 4; q++) {
                ulonglong2 t2 = ap[q];
                au[2 * q]     = t2.x;
                au[2 * q + 1] = t2.y;
            }
#pragma unroll
            for (int j = 0; j < 8; j++) bu[j] = Bs[k2 * LD + j * 16 + tx];
#pragma unroll
            for (int i = 0; i < 8; i++)
#pragma unroll
                for (int j = 0; j < 8; j++) fma2(acc[i][j], au[i], bu[j]);
        }
        __syncthreads();
    }

    // Epilogue: reduce even/odd-k lanes, add bias, optional sigmoid, coalesced store
    float bias[8];
#pragma unroll
    for (int j = 0; j < 8; j++) {
        int n = n0 + tx * 8 + j;
        bias[j] = b1[n] + (b2 ? b2[n] : 0.0f);
    }
#pragma unroll
    for (int i = 0; i < 8; i++) {
        float o[8];
#pragma unroll
        for (int j = 0; j < 8; j++) {
            float2 s = upk(acc[i][j]);
            float v = (s.x + s.y) + bias[j];
            if (SIG) v = sigm(v);
            o[j] = v;
        }
        float* cp = C + (size_t)(m0 + ty * 8 + i) * N + n0 + tx * 8;
        *(float4*)cp       = make_float4(o[0], o[1], o[2], o[3]);
        *(float4*)(cp + 4) = make_float4(o[4], o[5], o[6], o[7]);
    }
}

// K1: xg = x @ W_ih^T + (b_ih + b_hh)
__global__ void __launch_bounds__(256, 1)
k_xg(const float* __restrict__ x, const float* __restrict__ Wih,
     const float* __restrict__ bih, const float* __restrict__ bhh) {
    gemm_body<INPUT_, GATES_, false>(x, Wih, bih, bhh, g_xg);
}

// K3: out = sigmoid(hs @ W_out^T + b_out)
__global__ void __launch_bounds__(256, 1)
k_out(const float* __restrict__ Wout, const float* __restrict__ bout,
      float* __restrict__ out) {
    gemm_body<HID_, OUT_, true>(g_hs, Wout, bout, nullptr, out);
}

// K2: LSTM recurrence. One CTA per batch element; thread tid owns gate row tid.
__global__ void __launch_bounds__(256, 1)
k_lstm(const float* __restrict__ h0, const float* __restrict__ c0,
       const float* __restrict__ Whh,
       float* __restrict__ hT, float* __restrict__ cT) {
    const int b = blockIdx.x;
    const int tid = threadIdx.x;

    // W_hh row for this gate, packed as 32 f32x2 pairs (64 registers)
    unsigned long long w2[32];
    const float4* wr = (const float4*)(Whh + tid * HID_);
#pragma unroll
    for (int q = 0; q < 16; q++) {
        float4 v = wr[q];
        w2[2 * q]     = pk(v.x, v.y);
        w2[2 * q + 1] = pk(v.z, v.w);
    }

    __shared__ __align__(16) float hsh[HID_];
    __shared__ float act[GATES_];

    float c = 0.0f;
    if (tid < HID_) {
        hsh[tid] = h0[b * HID_ + tid];
        c = c0[b * HID_ + tid];
    }
    __syncthreads();

    const float* xp = g_xg + (size_t)b * GATES_ + tid;  // step stride BATCH*GATES_
    float xv = xp[0];

    for (int t = 0; t < T_STEPS; t++) {
        // Prefetch next step's gate pre-activation (hides DRAM latency)
        float xnext = 0.0f;
        if (t < T_STEPS - 1) xnext = xp[(size_t)(t + 1) * (BATCH * GATES_)];

        // gate = xv + dot(W_hh[tid,:], h)   via f32x2 packed FMAs
        unsigned long long a0 = 0ull, a1 = 0ull;
        const ulonglong2* hp = (const ulonglong2*)hsh;
#pragma unroll
        for (int q = 0; q < 16; q++) {
            ulonglong2 hh = hp[q];
            fma2(a0, w2[2 * q], hh.x);
            fma2(a1, w2[2 * q + 1], hh.y);
        }
        float2 s0 = upk(a0), s1 = upk(a1);
        float s = xv + ((s0.x + s0.y) + (s1.x + s1.y));

        // Gate order i,f,g,o: g (128..191) -> tanh, others -> sigmoid
        float a = (tid >= 128 && tid < 192) ? tanhf(s) : sigm(s);
        act[tid] = a;
        __syncthreads();

        if (tid < HID_) {
            float i_ = act[tid];
            float f_ = act[HID_ + tid];
            float g_ = act[2 * HID_ + tid];
            float o_ = act[3 * HID_ + tid];
            c = f_ * c + i_ * g_;
            float h = o_ * tanhf(c);
            hsh[tid] = h;
            g_hs[((size_t)t * BATCH + b) * HID_ + tid] = h;
        }
        __syncthreads();
        xv = xnext;
    }

    if (tid < HID_) {
        hT[b * HID_ + tid] = hsh[tid];
        cT[b * HID_ + tid] = c;
    }
}

extern "C" void kernel_launch(void* const* d_in, const int* in_sizes, int n_in,
                              void* d_out, int out_size) {
    const float* x    = (const float*)d_in[0];
    const float* h0   = (const float*)d_in[1];
    const float* c0   = (const float*)d_in[2];
    const float* Wih  = (const float*)d_in[3];
    const float* Whh  = (const float*)d_in[4];
    const float* bih  = (const float*)d_in[5];
    const float* bhh  = (const float*)d_in[6];
    const float* Wout = (const float*)d_in[7];
    const float* bout = (const float*)d_in[8];

    float* out = (float*)d_out;                 // (T, B, OUT)
    float* hT  = out + OUT_ELEMS;               // (1, B, HID)
    float* cT  = hT + HC_ELEMS;                 // (1, B, HID)

    // 1) xg = x @ W_ih^T + (b_ih + b_hh)
    k_xg<<<dim3(GATES_ / 128, M_ROWS / 128), 256>>>(x, Wih, bih, bhh);
    // 2) sequential LSTM recurrence (one CTA per batch element)
    k_lstm<<<BATCH, 256>>>(h0, c0, Whh, hT, cT);
    // 3) out = sigmoid(hs @ W_out^T + b_out)
    k_out<<<dim3(OUT_ / 128, M_ROWS / 128), 256>>>(Wout, bout, out);
}